// round 6
// baseline (speedup 1.0000x reference)
#include <cuda_runtime.h>
#include <cstdint>

#define NMAX 100000
#define DD 128

// Scratch buffers (allocation-free rule: __device__ globals)
__device__ float g_x[(size_t)NMAX * DD];   // h_in @ W
__device__ float g_deg[NMAX];
__device__ float g_dis[NMAX];

// ---------------------------------------------------------------------------
// init: zero the output accumulator (d_out) and set deg = 1 (self loop)
// ---------------------------------------------------------------------------
__global__ void init_kernel(float* __restrict__ out, int N) {
    int i = blockIdx.x * blockDim.x + threadIdx.x;
    int total4 = N * (DD / 4);
    if (i < total4) ((float4*)out)[i] = make_float4(0.f, 0.f, 0.f, 0.f);
    if (i < N) g_deg[i] = 1.0f;
}

// ---------------------------------------------------------------------------
// degree: in-degree via atomics on dst (edge_index is int32: JAX x64 disabled)
// ---------------------------------------------------------------------------
__global__ void deg_kernel(const int* __restrict__ ei, int E) {
    int e = blockIdx.x * blockDim.x + threadIdx.x;
    if (e < E) {
        int d = ei[E + e];
        if (d >= 0 && d < NMAX) atomicAdd(&g_deg[d], 1.0f);
    }
}

__global__ void dis_kernel(int N) {
    int i = blockIdx.x * blockDim.x + threadIdx.x;
    if (i < N) g_dis[i] = rsqrtf(g_deg[i]);
}

// ---------------------------------------------------------------------------
// GEMM: g_x = h_in (N,128) @ W (128,128), fp32
// Block = 256 threads, tile = 64 rows x 128 cols, thread tile = 8 rows x 4 cols
// A tile in static smem (32 KB). W read through L1 (64 KB, read-only, shared by
// all blocks on the SM -> near-100% L1 hits after warmup). No dynamic smem,
// no cudaFuncSetAttribute.
// ---------------------------------------------------------------------------
#define TILE_ROWS 64
__global__ void __launch_bounds__(256) gemm_kernel(
    const float* __restrict__ h, const float* __restrict__ W, int N)
{
    __shared__ float As[TILE_ROWS * DD];   // 32 KB

    int tid  = threadIdx.x;
    int lane = tid & 31;
    int wrp  = tid >> 5;

    int ntiles = (N + TILE_ROWS - 1) / TILE_ROWS;
    for (int t = blockIdx.x; t < ntiles; t += gridDim.x) {
        int row0 = t * TILE_ROWS;

        // Load A tile: 64 rows x 32 float4
        for (int idx = tid; idx < TILE_ROWS * 32; idx += 256) {
            int r = idx >> 5;
            int j = idx & 31;
            int grow = row0 + r;
            float4 v = (grow < N) ? ((const float4*)h)[(size_t)grow * 32 + j]
                                  : make_float4(0.f, 0.f, 0.f, 0.f);
            *(float4*)&As[r * DD + j * 4] = v;
        }
        __syncthreads();

        float acc[8][4];
        #pragma unroll
        for (int r = 0; r < 8; r++)
            #pragma unroll
            for (int j = 0; j < 4; j++) acc[r][j] = 0.f;

        int rbase = wrp * 8;       // rows this warp owns (broadcast LDS)
        int cbase = lane * 4;      // cols this lane owns

        #pragma unroll 4
        for (int k4 = 0; k4 < DD; k4 += 4) {
            float4 a[8];
            #pragma unroll
            for (int r = 0; r < 8; r++)
                a[r] = *(const float4*)&As[(rbase + r) * DD + k4];
            #pragma unroll
            for (int kk = 0; kk < 4; kk++) {
                float4 w4 = __ldg((const float4*)&W[(k4 + kk) * DD + cbase]);
                #pragma unroll
                for (int r = 0; r < 8; r++) {
                    float av = (kk == 0) ? a[r].x : (kk == 1) ? a[r].y
                             : (kk == 2) ? a[r].z : a[r].w;
                    acc[r][0] += av * w4.x;
                    acc[r][1] += av * w4.y;
                    acc[r][2] += av * w4.z;
                    acc[r][3] += av * w4.w;
                }
            }
        }

        #pragma unroll
        for (int r = 0; r < 8; r++) {
            int grow = row0 + rbase + r;
            if (grow < N) {
                *(float4*)&g_x[(size_t)grow * DD + cbase] =
                    make_float4(acc[r][0], acc[r][1], acc[r][2], acc[r][3]);
            }
        }
        __syncthreads();
    }
}

// ---------------------------------------------------------------------------
// Scatter: one warp per edge. out[dst] += dis[src]*dis[dst] * x[src]
// 128 floats per edge = 32 lanes x 4 scalar atomicAdd (return unused -> REDG).
// ---------------------------------------------------------------------------
__global__ void scatter_kernel(const int* __restrict__ ei,
                               float* __restrict__ out, int E)
{
    int gtid = blockIdx.x * blockDim.x + threadIdx.x;
    int e    = gtid >> 5;
    int lane = gtid & 31;
    if (e >= E) return;

    int s = ei[e];
    int d = ei[E + e];
    if ((unsigned)s >= NMAX || (unsigned)d >= NMAX) return;
    float norm = g_dis[s] * g_dis[d];

    float4 v = ((const float4*)&g_x[(size_t)s * DD])[lane];

    float* dst = &out[(size_t)d * DD + lane * 4];
    atomicAdd(dst + 0, norm * v.x);
    atomicAdd(dst + 1, norm * v.y);
    atomicAdd(dst + 2, norm * v.z);
    atomicAdd(dst + 3, norm * v.w);
}

// ---------------------------------------------------------------------------
// Finalize: self-loop term + bias + PReLU + LayerNorm. One warp per node row.
// ---------------------------------------------------------------------------
__global__ void final_kernel(float* __restrict__ out,
                             const float* __restrict__ bvec,
                             const float* __restrict__ prelu_a,
                             const float* __restrict__ gamma,
                             const float* __restrict__ beta,
                             int N)
{
    int gtid = blockIdx.x * blockDim.x + threadIdx.x;
    int i    = gtid >> 5;
    int lane = gtid & 31;
    if (i >= N) return;

    float4 acc = ((float4*)out)[(size_t)i * 32 + lane];
    float4 xv  = ((const float4*)g_x)[(size_t)i * 32 + lane];
    float  dis = g_dis[i];
    float  d2  = dis * dis;
    float4 bv  = ((const float4*)bvec)[lane];
    float  slope = prelu_a[0];

    float h0 = acc.x + d2 * xv.x + bv.x;
    float h1 = acc.y + d2 * xv.y + bv.y;
    float h2 = acc.z + d2 * xv.z + bv.z;
    float h3 = acc.w + d2 * xv.w + bv.w;

    h0 = (h0 >= 0.f) ? h0 : slope * h0;
    h1 = (h1 >= 0.f) ? h1 : slope * h1;
    h2 = (h2 >= 0.f) ? h2 : slope * h2;
    h3 = (h3 >= 0.f) ? h3 : slope * h3;

    float sum = h0 + h1 + h2 + h3;
    float sq  = h0*h0 + h1*h1 + h2*h2 + h3*h3;
    #pragma unroll
    for (int m = 16; m > 0; m >>= 1) {
        sum += __shfl_xor_sync(0xFFFFFFFFu, sum, m);
        sq  += __shfl_xor_sync(0xFFFFFFFFu, sq,  m);
    }
    float mu   = sum * (1.0f / 128.0f);
    float var  = sq * (1.0f / 128.0f) - mu * mu;
    float rstd = rsqrtf(var + 1e-5f);

    float4 gm = ((const float4*)gamma)[lane];
    float4 be = ((const float4*)beta)[lane];

    float4 o;
    o.x = (h0 - mu) * rstd * gm.x + be.x;
    o.y = (h1 - mu) * rstd * gm.y + be.y;
    o.z = (h2 - mu) * rstd * gm.z + be.z;
    o.w = (h3 - mu) * rstd * gm.w + be.w;

    ((float4*)out)[(size_t)i * 32 + lane] = o;
}

// ---------------------------------------------------------------------------
extern "C" void kernel_launch(void* const* d_in, const int* in_sizes, int n_in,
                              void* d_out, int out_size)
{
    const float* h_in  = (const float*)d_in[0];
    const int*   ei    = (const int*)d_in[1];     // int32 (JAX default x64 off)
    const float* W     = (const float*)d_in[2];
    const float* bvec  = (const float*)d_in[3];
    const float* pa    = (const float*)d_in[4];
    const float* gamma = (const float*)d_in[5];
    const float* beta  = (const float*)d_in[6];
    float*       out   = (float*)d_out;

    int N = in_sizes[0] / DD;
    int E = in_sizes[1] / 2;
    if (N > NMAX) N = NMAX;

    // 1) zero accumulator + deg=1
    {
        int threads = N * 32;
        init_kernel<<<(threads + 255) / 256, 256>>>(out, N);
    }
    // 2) degree
    deg_kernel<<<(E + 255) / 256, 256>>>(ei, E);
    // 3) dis = deg^-1/2
    dis_kernel<<<(N + 255) / 256, 256>>>(N);
    // 4) GEMM
    gemm_kernel<<<296, 256>>>(h_in, W, N);
    // 5) scatter-add messages
    {
        long long threads = (long long)E * 32;
        int blocks = (int)((threads + 255) / 256);
        scatter_kernel<<<blocks, 256>>>(ei, out, E);
    }
    // 6) self-loop + bias + PReLU + LayerNorm
    {
        int threads = N * 32;
        final_kernel<<<(threads + 255) / 256, 256>>>(out, bvec, pa, gamma, beta, N);
    }
}

// round 11
// speedup vs baseline: 1.8257x; 1.8257x over previous
#include <cuda_runtime.h>
#include <cstdint>

#define NMAX 100000
#define EMAX 1000000
#define DD 128

// Scratch (allocation-free rule: __device__ globals)
__device__ float g_x[(size_t)NMAX * DD];   // h_in @ W
__device__ float g_dis[NMAX];
__device__ int   g_cnt[NMAX];              // in-degree (no self loop)
__device__ int   g_fill[NMAX];
__device__ int   g_row[NMAX];              // CSR row start
__device__ int   g_part[1024];             // scan partials
__device__ int   g_csr[EMAX];              // src per (dst-sorted) edge

// ---------------------------------------------------------------------------
__global__ void zero_kernel(int N) {
    int i = blockIdx.x * blockDim.x + threadIdx.x;
    if (i < N) { g_cnt[i] = 0; g_fill[i] = 0; }
}

__global__ void count_kernel(const int* __restrict__ ei, int E) {
    int e = blockIdx.x * blockDim.x + threadIdx.x;
    if (e < E) {
        int d = ei[E + e];
        if ((unsigned)d < NMAX) atomicAdd(&g_cnt[d], 1);
    }
}

// ---------------- 3-step exclusive scan over g_cnt -> g_row ----------------
__global__ void scan_block(int N) {
    __shared__ int sh[1024];
    int i = blockIdx.x * 1024 + threadIdx.x;
    int v = (i < N) ? g_cnt[i] : 0;
    sh[threadIdx.x] = v;
    __syncthreads();
    for (int off = 1; off < 1024; off <<= 1) {
        int t = (threadIdx.x >= off) ? sh[threadIdx.x - off] : 0;
        __syncthreads();
        sh[threadIdx.x] += t;
        __syncthreads();
    }
    if (i < N) g_row[i] = sh[threadIdx.x] - v;           // exclusive
    if (threadIdx.x == 1023) g_part[blockIdx.x] = sh[1023];
}

__global__ void scan_part(int nb) {
    __shared__ int sh[1024];
    int v = (threadIdx.x < nb) ? g_part[threadIdx.x] : 0;
    sh[threadIdx.x] = v;
    __syncthreads();
    for (int off = 1; off < 1024; off <<= 1) {
        int t = (threadIdx.x >= off) ? sh[threadIdx.x - off] : 0;
        __syncthreads();
        sh[threadIdx.x] += t;
        __syncthreads();
    }
    if (threadIdx.x < nb) g_part[threadIdx.x] = sh[threadIdx.x] - v;
}

__global__ void scan_add(int N) {
    int i = blockIdx.x * 1024 + threadIdx.x;
    if (i < N) g_row[i] += g_part[blockIdx.x];
}

// ---------------------------------------------------------------------------
__global__ void dis_kernel(int N) {
    int i = blockIdx.x * blockDim.x + threadIdx.x;
    if (i < N) g_dis[i] = rsqrtf((float)g_cnt[i] + 1.0f);  // +1 self loop
}

__global__ void fill_kernel(const int* __restrict__ ei, int E) {
    int e = blockIdx.x * blockDim.x + threadIdx.x;
    if (e < E) {
        int s = ei[e];
        int d = ei[E + e];
        if ((unsigned)s >= NMAX || (unsigned)d >= NMAX) return;
        int slot = g_row[d] + atomicAdd(&g_fill[d], 1);
        if (slot < EMAX) g_csr[slot] = s;
    }
}

// ---------------------------------------------------------------------------
// GEMM: g_x = h_in (N,128) @ W (128,128), fp32 (FFMA-roofline bound, 87us)
// ---------------------------------------------------------------------------
#define TILE_ROWS 64
__global__ void __launch_bounds__(256) gemm_kernel(
    const float* __restrict__ h, const float* __restrict__ W, int N)
{
    __shared__ float As[TILE_ROWS * DD];   // 32 KB

    int tid  = threadIdx.x;
    int lane = tid & 31;
    int wrp  = tid >> 5;

    int ntiles = (N + TILE_ROWS - 1) / TILE_ROWS;
    for (int t = blockIdx.x; t < ntiles; t += gridDim.x) {
        int row0 = t * TILE_ROWS;

        for (int idx = tid; idx < TILE_ROWS * 32; idx += 256) {
            int r = idx >> 5;
            int j = idx & 31;
            int grow = row0 + r;
            float4 v = (grow < N) ? ((const float4*)h)[(size_t)grow * 32 + j]
                                  : make_float4(0.f, 0.f, 0.f, 0.f);
            *(float4*)&As[r * DD + j * 4] = v;
        }
        __syncthreads();

        float acc[8][4];
        #pragma unroll
        for (int r = 0; r < 8; r++)
            #pragma unroll
            for (int j = 0; j < 4; j++) acc[r][j] = 0.f;

        int rbase = wrp * 8;
        int cbase = lane * 4;

        #pragma unroll 4
        for (int k4 = 0; k4 < DD; k4 += 4) {
            float4 a[8];
            #pragma unroll
            for (int r = 0; r < 8; r++)
                a[r] = *(const float4*)&As[(rbase + r) * DD + k4];
            #pragma unroll
            for (int kk = 0; kk < 4; kk++) {
                float4 w4 = __ldg((const float4*)&W[(k4 + kk) * DD + cbase]);
                #pragma unroll
                for (int r = 0; r < 8; r++) {
                    float av = (kk == 0) ? a[r].x : (kk == 1) ? a[r].y
                             : (kk == 2) ? a[r].z : a[r].w;
                    acc[r][0] += av * w4.x;
                    acc[r][1] += av * w4.y;
                    acc[r][2] += av * w4.z;
                    acc[r][3] += av * w4.w;
                }
            }
        }

        #pragma unroll
        for (int r = 0; r < 8; r++) {
            int grow = row0 + rbase + r;
            if (grow < N) {
                *(float4*)&g_x[(size_t)grow * DD + cbase] =
                    make_float4(acc[r][0], acc[r][1], acc[r][2], acc[r][3]);
            }
        }
        __syncthreads();
    }
}

// ---------------------------------------------------------------------------
// Fused aggregate + epilogue: one warp per node.
// acc = dis^2 * x[i] + sum_{edges to i} dis[s]*dis[i]*x[s]; then bias, PReLU,
// LayerNorm, single store to out. No atomics, gathers hit L2 (g_x ~51MB).
// ---------------------------------------------------------------------------
__global__ void agg_kernel(float* __restrict__ out,
                           const float* __restrict__ bvec,
                           const float* __restrict__ prelu_a,
                           const float* __restrict__ gamma,
                           const float* __restrict__ beta,
                           int N)
{
    int gtid = blockIdx.x * blockDim.x + threadIdx.x;
    int i    = gtid >> 5;
    int lane = gtid & 31;
    if (i >= N) return;

    float di    = g_dis[i];
    int   start = g_row[i];
    int   len   = g_cnt[i];

    // self loop
    float4 xv = ((const float4*)g_x)[(size_t)i * 32 + lane];
    float  d2 = di * di;
    float a0 = d2 * xv.x, a1 = d2 * xv.y, a2 = d2 * xv.z, a3 = d2 * xv.w;

    for (int k = 0; k < len; k++) {
        int   s    = g_csr[start + k];
        float norm = di * g_dis[s];
        float4 v = ((const float4*)g_x)[(size_t)s * 32 + lane];
        a0 += norm * v.x;
        a1 += norm * v.y;
        a2 += norm * v.z;
        a3 += norm * v.w;
    }

    float4 bv = ((const float4*)bvec)[lane];
    float slope = prelu_a[0];

    float h0 = a0 + bv.x, h1 = a1 + bv.y, h2 = a2 + bv.z, h3 = a3 + bv.w;
    h0 = (h0 >= 0.f) ? h0 : slope * h0;
    h1 = (h1 >= 0.f) ? h1 : slope * h1;
    h2 = (h2 >= 0.f) ? h2 : slope * h2;
    h3 = (h3 >= 0.f) ? h3 : slope * h3;

    float sum = h0 + h1 + h2 + h3;
    float sq  = h0*h0 + h1*h1 + h2*h2 + h3*h3;
    #pragma unroll
    for (int m = 16; m > 0; m >>= 1) {
        sum += __shfl_xor_sync(0xFFFFFFFFu, sum, m);
        sq  += __shfl_xor_sync(0xFFFFFFFFu, sq,  m);
    }
    float mu   = sum * (1.0f / 128.0f);
    float var  = sq * (1.0f / 128.0f) - mu * mu;
    float rstd = rsqrtf(var + 1e-5f);

    float4 gm = ((const float4*)gamma)[lane];
    float4 be = ((const float4*)beta)[lane];

    float4 o;
    o.x = (h0 - mu) * rstd * gm.x + be.x;
    o.y = (h1 - mu) * rstd * gm.y + be.y;
    o.z = (h2 - mu) * rstd * gm.z + be.z;
    o.w = (h3 - mu) * rstd * gm.w + be.w;

    ((float4*)out)[(size_t)i * 32 + lane] = o;
}

// ---------------------------------------------------------------------------
extern "C" void kernel_launch(void* const* d_in, const int* in_sizes, int n_in,
                              void* d_out, int out_size)
{
    const float* h_in  = (const float*)d_in[0];
    const int*   ei    = (const int*)d_in[1];     // int32 (JAX default x64 off)
    const float* W     = (const float*)d_in[2];
    const float* bvec  = (const float*)d_in[3];
    const float* pa    = (const float*)d_in[4];
    const float* gamma = (const float*)d_in[5];
    const float* beta  = (const float*)d_in[6];
    float*       out   = (float*)d_out;

    int N = in_sizes[0] / DD;
    int E = in_sizes[1] / 2;
    if (N > NMAX) N = NMAX;
    if (E > EMAX) E = EMAX;

    int nb1024 = (N + 1023) / 1024;

    // CSR build
    zero_kernel<<<(N + 255) / 256, 256>>>(N);
    count_kernel<<<(E + 255) / 256, 256>>>(ei, E);
    scan_block<<<nb1024, 1024>>>(N);
    scan_part<<<1, 1024>>>(nb1024);
    scan_add<<<nb1024, 1024>>>(N);
    dis_kernel<<<(N + 255) / 256, 256>>>(N);
    fill_kernel<<<(E + 255) / 256, 256>>>(ei, E);

    // GEMM
    gemm_kernel<<<296, 256>>>(h_in, W, N);

    // Fused aggregate + bias + PReLU + LayerNorm
    {
        int threads = N * 32;
        agg_kernel<<<(threads + 255) / 256, 256>>>(out, bvec, pa, gamma, beta, N);
    }
}